// round 6
// baseline (speedup 1.0000x reference)
#include <cuda_runtime.h>
#include <cuda_fp16.h>
#include <cuda_fp8.h>
#include <cstdint>
#include <math.h>

#define M_DIM 16384
#define K_DIM 4096
#define N_DIM 4096

// fp8 copies of inputs + lse partials (static device scratch)
static __device__ unsigned char g_x8[(size_t)M_DIM * K_DIM];
static __device__ unsigned char g_w8[(size_t)N_DIM * K_DIM];   // W * 64, e4m3
static __device__ float2 g_part[(size_t)M_DIM * 8];            // [row][nslice]

// ---------------- tile / smem geometry ----------------
constexpr int BM = 128;            // M tile per CTA
constexpr int BN = 256;            // N chunk per fold
constexpr int NSLICE = 8;          // N split across CTAs
constexpr int NS_COLS = N_DIM / NSLICE;      // 512
constexpr int NCHUNK_CTA = NS_COLS / BN;     // 2
constexpr int BK = 128;            // K fp8 elements per stage (128 B/row, SW128)
constexpr int NSTAGE = 4;
constexpr int KSTG = K_DIM / BK;             // 32
constexpr int TOTSTG = NCHUNK_CTA * KSTG;    // 64 stages per CTA

constexpr uint32_t A_STG = BM * 128;         // 16 KB
constexpr uint32_t B_STG = BN * 128;         // 32 KB
constexpr uint32_t STG   = A_STG + B_STG;    // 48 KB
constexpr uint32_t SMEM_BYTES = NSTAGE * STG + 1024;   // 197632

constexpr float W_SCALE_INV = 1.0f / 64.0f;  // undo the 2^6 W pre-scale

__device__ __forceinline__ uint32_t smem_u32(const void* p) {
    uint32_t a;
    asm("{ .reg .u64 t; cvta.to.shared.u64 t, %1; cvt.u32.u64 %0, t; }"
        : "=r"(a) : "l"(p));
    return a;
}
__device__ __forceinline__ uint32_t swz(uint32_t off) {   // SW128, 16B granule
    return off ^ ((off >> 3) & 0x70);
}
__device__ __forceinline__ void cp_async16(uint32_t dst, const void* src) {
    asm volatile("cp.async.cg.shared.global [%0], [%1], 16;"
                 :: "r"(dst), "l"(__cvta_generic_to_global(src)) : "memory");
}
#define CP_COMMIT() asm volatile("cp.async.commit_group;" ::: "memory")
#define CP_WAIT(n)  asm volatile("cp.async.wait_group %0;" :: "n"(n) : "memory")

__device__ __forceinline__ void ldsm4(uint32_t* r, uint32_t addr) {
    asm volatile("ldmatrix.sync.aligned.m8n8.x4.shared.b16 {%0,%1,%2,%3}, [%4];"
                 : "=r"(r[0]), "=r"(r[1]), "=r"(r[2]), "=r"(r[3]) : "r"(addr));
}
// fp8 MMA: m16n8k32, e4m3 x e4m3 -> f32
__device__ __forceinline__ void mma16832_f8(float* c, const uint32_t* a, const uint32_t* b) {
    asm volatile(
        "mma.sync.aligned.m16n8k32.row.col.f32.e4m3.e4m3.f32 "
        "{%0,%1,%2,%3}, {%4,%5,%6,%7}, {%8,%9}, {%0,%1,%2,%3};"
        : "+f"(c[0]), "+f"(c[1]), "+f"(c[2]), "+f"(c[3])
        : "r"(a[0]), "r"(a[1]), "r"(a[2]), "r"(a[3]), "r"(b[0]), "r"(b[1]));
}

// ---------------- fp32 -> e4m3 conversion ----------------
__global__ void __launch_bounds__(256) cvt_x8_kernel(const float4* __restrict__ src, int n4) {
    int i = blockIdx.x * 256 + threadIdx.x;
    if (i >= n4) return;
    float4 v = src[i];
    uint32_t lo = __nv_cvt_float2_to_fp8x2(make_float2(v.x, v.y), __NV_SATFINITE, __NV_E4M3);
    uint32_t hi = __nv_cvt_float2_to_fp8x2(make_float2(v.z, v.w), __NV_SATFINITE, __NV_E4M3);
    reinterpret_cast<uint32_t*>(g_x8)[i] = lo | (hi << 16);
}
__global__ void __launch_bounds__(256) cvt_w8_kernel(const float4* __restrict__ src, int n4) {
    int i = blockIdx.x * 256 + threadIdx.x;
    if (i >= n4) return;
    float4 v = src[i];
    uint32_t lo = __nv_cvt_float2_to_fp8x2(make_float2(v.x * 64.f, v.y * 64.f), __NV_SATFINITE, __NV_E4M3);
    uint32_t hi = __nv_cvt_float2_to_fp8x2(make_float2(v.z * 64.f, v.w * 64.f), __NV_SATFINITE, __NV_E4M3);
    reinterpret_cast<uint32_t*>(g_w8)[i] = lo | (hi << 16);
}

// ---------------- GEMM + partial logsumexp (per N-slice) ----------------
__global__ void __launch_bounds__(512, 1)
gemm_lse_part_kernel(const float* __restrict__ bias) {
    extern __shared__ char smem_raw[];
    const uint32_t sb0 = smem_u32(smem_raw);
    const uint32_t sb  = (sb0 + 1023u) & ~1023u;   // 1024-align
    char* sptr = smem_raw + (sb - sb0);

    const int tid  = threadIdx.x;
    const int wid  = tid >> 5;            // 0..15
    const int lane = tid & 31;
    const int mt   = blockIdx.x >> 3;     // m-tile (8 consecutive CTAs share A)
    const int ns   = blockIdx.x & 7;      // n-slice
    const int m0   = mt * BM;
    const int n0   = ns * NS_COLS;

    const int warpM = (wid >> 3) * 64;    // 0 or 64
    const int warpN = (wid & 7) * 32;     // 0..224 within BN

    // per-lane ldmatrix byte offsets (pre-swizzle) — identical to fp16 case
    const int matid = lane >> 3, rin = lane & 7;
    int aRow[4], bRow[2];
    #pragma unroll
    for (int mi = 0; mi < 4; mi++)
        aRow[mi] = (warpM + mi * 16 + (matid & 1) * 8 + rin) * 128 + (matid >> 1) * 16;
    #pragma unroll
    for (int p = 0; p < 2; p++)
        bRow[p] = (warpN + p * 16 + (matid >> 1) * 8 + rin) * 128 + (matid & 1) * 16;

    // producer: 3072 x 16B per stage, 6 per thread (rows are K128 fp8 = 128 B)
    auto issue_stage = [&](int gs) {
        if (gs < TOTSTG) {
            const int slot  = gs & (NSTAGE - 1);
            const int chunk = gs >> 5;            // 0..1 (KSTG=32)
            const int ks    = gs & 31;
            const int kg    = ks * BK;
            const int nb    = n0 + chunk * BN;
            const uint32_t aB = sb + slot * STG;
            const uint32_t bB = aB + A_STG;
            #pragma unroll
            for (int j = 0; j < 6; j++) {
                const int c   = tid + 512 * j;    // 0..3071
                const bool isA = c < 1024;
                const int rc  = isA ? c : c - 1024;
                const int row = rc >> 3;
                const int c16 = rc & 7;
                const unsigned char* src = isA
                    ? g_x8 + ((size_t)(m0 + row) * K_DIM + kg + c16 * 16)
                    : g_w8 + ((size_t)(nb + row) * K_DIM + kg + c16 * 16);
                cp_async16((isA ? aB : bB) + swz((uint32_t)(row * 128 + c16 * 16)), src);
            }
        }
        CP_COMMIT();
    };

    // f32 accumulators: 4 m-tiles x 4 n-tiles x 4
    float acc[4][4][4];
    #pragma unroll
    for (int mi = 0; mi < 4; mi++)
        #pragma unroll
        for (int ni = 0; ni < 4; ni++)
            #pragma unroll
            for (int r = 0; r < 4; r++) acc[mi][ni][r] = 0.f;

    float rm[8], rs[8];
    #pragma unroll
    for (int s = 0; s < 8; s++) { rm[s] = -1e30f; rs[s] = 0.f; }

    issue_stage(0); issue_stage(1); issue_stage(2);

    const int tg = lane & 3;

    for (int chunk = 0; chunk < NCHUNK_CTA; ++chunk) {
        #pragma unroll 1
        for (int ks = 0; ks < KSTG; ++ks) {
            const int gs = chunk * KSTG + ks;
            CP_WAIT(NSTAGE - 2);
            __syncthreads();
            issue_stage(gs + NSTAGE - 1);

            const int slot = gs & (NSTAGE - 1);
            const uint32_t aB = sb + slot * STG;
            const uint32_t bB = aB + A_STG;
            #pragma unroll
            for (int g = 0; g < 4; g++) {        // 4 x K32 per stage
                uint32_t af[4][4], bt[2][4];
                #pragma unroll
                for (int mi = 0; mi < 4; mi++)
                    ldsm4(af[mi], aB + swz((uint32_t)(aRow[mi] + g * 32)));
                #pragma unroll
                for (int p = 0; p < 2; p++)
                    ldsm4(bt[p], bB + swz((uint32_t)(bRow[p] + g * 32)));
                #pragma unroll
                for (int mi = 0; mi < 4; mi++) {
                    mma16832_f8(acc[mi][0], af[mi], &bt[0][0]);
                    mma16832_f8(acc[mi][1], af[mi], &bt[0][2]);
                    mma16832_f8(acc[mi][2], af[mi], &bt[1][0]);
                    mma16832_f8(acc[mi][3], af[mi], &bt[1][2]);
                }
            }
        }

        // fold chunk logits into running (max, sum); undo W 2^6 pre-scale
        float bv[4][2];
        #pragma unroll
        for (int ni = 0; ni < 4; ni++) {
            const int nc = n0 + chunk * BN + warpN + ni * 8 + tg * 2;
            bv[ni][0] = bias[nc];
            bv[ni][1] = bias[nc + 1];
        }
        #pragma unroll
        for (int mi = 0; mi < 4; mi++) {
            #pragma unroll
            for (int h = 0; h < 2; h++) {
                const int s = mi * 2 + h;
                float v[8], lm = rm[s];
                #pragma unroll
                for (int ni = 0; ni < 4; ni++) {
                    #pragma unroll
                    for (int c = 0; c < 2; c++) {
                        v[ni * 2 + c] = acc[mi][ni][h * 2 + c] * W_SCALE_INV + bv[ni][c];
                        lm = fmaxf(lm, v[ni * 2 + c]);
                        acc[mi][ni][h * 2 + c] = 0.f;
                    }
                }
                float e = 0.f;
                #pragma unroll
                for (int j = 0; j < 8; j++) e += __expf(v[j] - lm);
                rs[s] = rs[s] * __expf(rm[s] - lm) + e;
                rm[s] = lm;
            }
        }
    }

    // cross-thread reduction: quad shuffle, then across 8 N-warps via smem
    __syncthreads();
    float2* red = reinterpret_cast<float2*>(sptr);   // 128 rows x 8 warps
    #pragma unroll
    for (int s = 0; s < 8; s++) {
        float m = rm[s], sm = rs[s];
        #pragma unroll
        for (int d = 1; d <= 2; d <<= 1) {
            float om = __shfl_xor_sync(0xffffffffu, m, d);
            float os = __shfl_xor_sync(0xffffffffu, sm, d);
            float nm = fmaxf(m, om);
            sm = sm * __expf(m - nm) + os * __expf(om - nm);
            m = nm;
        }
        if (tg == 0) {
            const int mi = s >> 1, h = s & 1;
            const int row = warpM + mi * 16 + (lane >> 2) + h * 8;
            red[row * 8 + (wid & 7)] = make_float2(m, sm);
        }
    }
    __syncthreads();

    if (tid < BM) {
        float m = -1e30f, sm = 0.f;
        #pragma unroll
        for (int w = 0; w < 8; w++) {
            float2 p = red[tid * 8 + w];
            float nm = fmaxf(m, p.x);
            sm = sm * __expf(m - nm) + p.y * __expf(p.x - nm);
            m = nm;
        }
        g_part[(size_t)(m0 + tid) * 8 + ns] = make_float2(m, sm);
    }
}

// ---------------- combine partials + activations ----------------
__global__ void __launch_bounds__(256) combine_kernel(float* __restrict__ out) {
    const int i = blockIdx.x * 256 + threadIdx.x;
    if (i >= M_DIM) return;
    float m = -1e30f, sm = 0.f;
    #pragma unroll
    for (int ns = 0; ns < 8; ns++) {       // fixed order -> deterministic
        float2 p = g_part[(size_t)i * 8 + ns];
        float nm = fmaxf(m, p.x);
        sm = sm * __expf(m - nm) + p.y * __expf(p.x - nm);
        m = nm;
    }
    float v = m + logf(sm);
    v = v > 0.f ? v : 0.01f * v;           // LeakyReLU x2
    v = v > 0.f ? v : 0.01f * v;
    v = v * 0.5f * (1.0f + erff(v * 0.70710678118654752f));   // GELU x2
    v = v * 0.5f * (1.0f + erff(v * 0.70710678118654752f));
    out[i] = v;
}

extern "C" void kernel_launch(void* const* d_in, const int* in_sizes, int n_in,
                              void* d_out, int out_size) {
    const float* x = (const float*)d_in[0];
    const float* W = (const float*)d_in[1];
    const float* b = (const float*)d_in[2];
    float* out = (float*)d_out;

    cudaFuncSetAttribute(gemm_lse_part_kernel,
                         cudaFuncAttributeMaxDynamicSharedMemorySize, SMEM_BYTES);

    const int x4 = (M_DIM * K_DIM) / 4;
    const int w4 = (N_DIM * K_DIM) / 4;
    cvt_x8_kernel<<<(x4 + 255) / 256, 256>>>((const float4*)x, x4);
    cvt_w8_kernel<<<(w4 + 255) / 256, 256>>>((const float4*)W, w4);
    gemm_lse_part_kernel<<<(M_DIM / BM) * NSLICE, 512, SMEM_BYTES>>>(b);
    combine_kernel<<<(M_DIM + 255) / 256, 256>>>(out);
}